// round 9
// baseline (speedup 1.0000x reference)
#include <cuda_runtime.h>
#include <cstdint>

// Problem constants
#define N_TOK   8192
#define DIM     4096
#define N_EXP   64
#define TOPK    2
#define CAP     160           // ceil(1.25 * 8192 / 64)
#define NEC     ((size_t)N_TOK * N_EXP * CAP)   // 83,886,080

#define GEMM_BLOCKS 128
#define ZERO_BLOCKS 20        // 128 + 20 = 148 = one full wave on GB300
#define GRID_TOTAL  (GEMM_BLOCKS + ZERO_BLOCKS)

// Scratch (device globals; no allocation allowed)
__device__ int   g_topk_idx[N_TOK * TOPK];
__device__ float g_topk_val[N_TOK * TOPK];
__device__ int   g_counts[N_EXP];
__device__ float g_colsum[N_EXP];

// packed fp32x2 FMA (sm_103a FFMA2): d.lo += a.lo*b.lo, d.hi += a.hi*b.hi
__device__ __forceinline__ void fma2(unsigned long long& d,
                                     unsigned long long a,
                                     unsigned long long b) {
    asm("fma.rn.f32x2 %0, %1, %2, %0;" : "+l"(d) : "l"(a), "l"(b));
}
__device__ __forceinline__ float ull_lo(unsigned long long a) {
    return __uint_as_float((unsigned)(a & 0xffffffffu));
}
__device__ __forceinline__ float ull_hi(unsigned long long a) {
    return __uint_as_float((unsigned)(a >> 32));
}

// ---------------------------------------------------------------------------
// Kernel 1: fused [zero-fill of mask+combine] + [GEMM + softmax + top-2].
// Grid = 148 blocks x 512 threads (one wave).
//   blocks [0,128):  GEMM block tile 64 rows x 64 experts, intra-block
//                    split-K: thread group 0 (tid<256) does even 32-wide
//                    K chunks, group 1 odd chunks. Per-group double-buffered
//                    smem + per-group NAMED barriers -> groups never
//                    serialize each other; 16 warps/SM (4/SMSP) hide LDS/FMA
//                    latency. Per-thread tile 4x4 with broadcast A reads.
//   blocks [128,148): grid-stride float4 zero-fill of the 671MB
//                    mask+combine region, hidden under the GEMM (DRAM ~7%).
// ---------------------------------------------------------------------------
__global__ __launch_bounds__(512)
void gemm_topk_kernel(const float* __restrict__ x,
                      const float* __restrict__ gw,
                      float* __restrict__ probs_out,
                      float* __restrict__ zero_base) {
    const int tid = threadIdx.x;

    // ---- zero-fill blocks --------------------------------------------------
    if (blockIdx.x >= GEMM_BLOCKS) {
        float4* p = (float4*)zero_base;
        const size_t n4 = (2 * NEC) / 4;                 // 41,943,040 float4
        const float4 z = make_float4(0.f, 0.f, 0.f, 0.f);
        size_t i = (size_t)(blockIdx.x - GEMM_BLOCKS) * 512 + tid;
        for (; i < n4; i += (size_t)ZERO_BLOCKS * 512)
            p[i] = z;
        return;
    }

    // ---- GEMM blocks -------------------------------------------------------
    extern __shared__ float smem[];      // 16384 floats = 64KB
    // group kg buffers: [kg*8192 .. kg*8192+8191], two 4096-float bufs,
    // each buf = X(2048) | W(2048)

    const int kg = tid >> 8;             // k-parity group 0/1
    const int lt = tid & 255;            // id within group
    const int rowBase = blockIdx.x * 64;
    const int rg = lt >> 4;              // 0..15 -> rows rg*4 .. rg*4+3
    const int cg = lt & 15;              // cols cg, cg+16, cg+32, cg+48
    const int row0 = rg * 4;
    const int swzA = (rg & 7) << 2;      // ((row>>2)&7)<<2 for rows row0..+3
    const int swzB = (cg & 7) << 2;      // (col&7)<<2 for all 4 cols
    float* const grp = smem + kg * 8192;

    const float* xg = x + (size_t)rowBase * DIM;

    // staging: 2 float4 per thread per matrix per chunk (512 float4 each)
    int xoff[2], woff[2], gidx[2];
#pragma unroll
    for (int j = 0; j < 2; j++) {
        const int f = lt + j * 256;      // 0..511
        const int r = f >> 3;            // row/expert 0..63
        const int kq = (f & 7) * 4;      // float offset in 32-float row
        xoff[j] = (r * 32 + kq) ^ (((r >> 2) & 7) << 2);  // A swizzle
        woff[j] = (r * 32 + kq) ^ ((r & 7) << 2);         // B swizzle
        gidx[j] = r * DIM + kq;
    }

    unsigned long long acc[4][4];
#pragma unroll
    for (int r = 0; r < 4; r++)
#pragma unroll
        for (int c = 0; c < 4; c++) acc[r][c] = 0ull;

    float4 xr[2], wr[2];
    {   // prologue: this group's first chunk (kc = kg)
        const float* xp = xg + kg * 32;
        const float* wp = gw + kg * 32;
#pragma unroll
        for (int j = 0; j < 2; j++) {
            xr[j] = *(const float4*)&xp[gidx[j]];
            wr[j] = *(const float4*)&wp[gidx[j]];
        }
    }

#pragma unroll 1
    for (int kc = kg; kc < 128; kc += 2) {
        float* Xb = grp + ((kc >> 1) & 1) * 4096;
        float* Wb = Xb + 2048;
#pragma unroll
        for (int j = 0; j < 2; j++) {
            *(float4*)&Xb[xoff[j]] = xr[j];
            *(float4*)&Wb[woff[j]] = wr[j];
        }
        // group-local barrier (id 1 for group0, id 2 for group1), 256 threads
        asm volatile("bar.sync %0, %1;" :: "r"(kg + 1), "r"(256) : "memory");

        if (kc + 2 < 128) {
            const float* xp = xg + (kc + 2) * 32;
            const float* wp = gw + (kc + 2) * 32;
#pragma unroll
            for (int j = 0; j < 2; j++) {
                xr[j] = *(const float4*)&xp[gidx[j]];
                wr[j] = *(const float4*)&wp[gidx[j]];
            }
        }

#pragma unroll
        for (int k = 0; k < 32; k += 4) {
            // B: 16 distinct addrs/warp (2-way lane pairing) -> 2 cyc each
            ulonglong2 B0 = *(const ulonglong2*)&Wb[((cg +  0) * 32 + k) ^ swzB];
            ulonglong2 B1 = *(const ulonglong2*)&Wb[((cg + 16) * 32 + k) ^ swzB];
            ulonglong2 B2 = *(const ulonglong2*)&Wb[((cg + 32) * 32 + k) ^ swzB];
            ulonglong2 B3 = *(const ulonglong2*)&Wb[((cg + 48) * 32 + k) ^ swzB];
#pragma unroll
            for (int r = 0; r < 4; r++) {
                // A: 16-lane broadcast, 2 distinct addrs -> 1 cyc
                ulonglong2 A = *(const ulonglong2*)&Xb[((row0 + r) * 32 + k) ^ swzA];
                fma2(acc[r][0], A.x, B0.x); fma2(acc[r][0], A.y, B0.y);
                fma2(acc[r][1], A.x, B1.x); fma2(acc[r][1], A.y, B1.y);
                fma2(acc[r][2], A.x, B2.x); fma2(acc[r][2], A.y, B2.y);
                fma2(acc[r][3], A.x, B3.x); fma2(acc[r][3], A.y, B3.y);
            }
        }
        // next iteration's stores hit the other buffer of THIS group; the
        // group barrier above proves all its reads completed.
    }

    // all 512 threads: wait for both groups' compute before reusing smem
    __syncthreads();

    // each group writes its partial logits; group0 -> lgA, group1 -> lgB
    float* lg = smem + kg * 4352;        // 64 rows, stride 68
#pragma unroll
    for (int r = 0; r < 4; r++)
#pragma unroll
        for (int c = 0; c < 4; c++)
            lg[(row0 + r) * 68 + cg + c * 16] =
                ull_lo(acc[r][c]) + ull_hi(acc[r][c]);
    __syncthreads();

    // per-row softmax + top-2: warp w (0..15) handles rows w*4 .. w*4+3
    const int lane = tid & 31;
    const int w = tid >> 5;
    for (int rr = 0; rr < 4; rr++) {
        const int r = w * 4 + rr;
        float2 a = *(float2*)&smem[r * 68 + lane * 2];
        float2 b = *(float2*)&smem[4352 + r * 68 + lane * 2];
        float v0 = a.x + b.x, v1 = a.y + b.y;

        float m = fmaxf(v0, v1);
#pragma unroll
        for (int off = 16; off; off >>= 1)
            m = fmaxf(m, __shfl_xor_sync(0xffffffffu, m, off));

        float e0 = expf(v0 - m), e1 = expf(v1 - m);
        float s = e0 + e1;
#pragma unroll
        for (int off = 16; off; off >>= 1)
            s += __shfl_xor_sync(0xffffffffu, s, off);
        float inv = 1.0f / s;

        const int gtok = rowBase + r;
        *(float2*)&probs_out[(size_t)gtok * N_EXP + lane * 2] =
            make_float2(e0 * inv, e1 * inv);

        // top-1 (ties -> lower index, matching jax top_k)
        float cv; int ci;
        if (v0 >= v1) { cv = v0; ci = lane * 2; } else { cv = v1; ci = lane * 2 + 1; }
#pragma unroll
        for (int off = 16; off; off >>= 1) {
            float ov = __shfl_xor_sync(0xffffffffu, cv, off);
            int   oi = __shfl_xor_sync(0xffffffffu, ci, off);
            if (ov > cv || (ov == cv && oi < ci)) { cv = ov; ci = oi; }
        }
        const float t1v = cv; const int t1i = ci;

        // top-2: lane holding t1i offers its other column
        if (lane * 2 == t1i)          { cv = v1; ci = lane * 2 + 1; }
        else if (lane * 2 + 1 == t1i) { cv = v0; ci = lane * 2; }
        else if (v0 >= v1)            { cv = v0; ci = lane * 2; }
        else                          { cv = v1; ci = lane * 2 + 1; }
#pragma unroll
        for (int off = 16; off; off >>= 1) {
            float ov = __shfl_xor_sync(0xffffffffu, cv, off);
            int   oi = __shfl_xor_sync(0xffffffffu, ci, off);
            if (ov > cv || (ov == cv && oi < ci)) { cv = ov; ci = oi; }
        }
        const float t2v = cv; const int t2i = ci;

        if (lane == 0) {
            float rr2 = expf(t2v - t1v);
            float inv2 = 1.0f / (1.0f + rr2);
            g_topk_idx[2 * gtok]     = t1i;
            g_topk_idx[2 * gtok + 1] = t2i;
            g_topk_val[2 * gtok]     = inv2;
            g_topk_val[2 * gtok + 1] = rr2 * inv2;
        }
    }
}

// ---------------------------------------------------------------------------
// Kernel 2: one block per expert. Ordered prefix count over the flat (N*K)
// assignment list (token-major, matching reference cumsum), scatter kept
// entries, record total count, deterministic column-sum of probs.
// ---------------------------------------------------------------------------
__global__ __launch_bounds__(256)
void scan_scatter_kernel(float* __restrict__ mask,
                         float* __restrict__ combine,
                         const float* __restrict__ probs) {
    const int e = blockIdx.x;
    const int tid = threadIdx.x;
    const int lane = tid & 31;
    const int w = tid >> 5;
    __shared__ int   wsum[8];
    __shared__ float fsum[8];

    int running = 0;
    for (int base = 0; base < N_TOK * TOPK; base += 256) {
        const int i = base + tid;
        const bool m = (g_topk_idx[i] == e);
        const unsigned bal = __ballot_sync(0xffffffffu, m);
        if (lane == 0) wsum[w] = __popc(bal);
        __syncthreads();
        int woff = 0, tot = 0;
#pragma unroll
        for (int j = 0; j < 8; j++) {
            int t = wsum[j];
            if (j < w) woff += t;
            tot += t;
        }
        if (m) {
            const int slot = running + woff + __popc(bal & ((1u << lane) - 1u));
            if (slot < CAP) {
                const int tok = i >> 1;
                const size_t o = (size_t)tok * (N_EXP * CAP) + e * CAP + slot;
                mask[o] = 1.0f;
                combine[o] = g_topk_val[i];
            }
        }
        running += tot;
        __syncthreads();
    }
    if (tid == 0) g_counts[e] = running;

    // deterministic column sum of probs[:, e]
    float s = 0.0f;
    for (int t = tid; t < N_TOK; t += 256)
        s += probs[(size_t)t * N_EXP + e];
#pragma unroll
    for (int off = 16; off; off >>= 1)
        s += __shfl_xor_sync(0xffffffffu, s, off);
    if (lane == 0) fsum[w] = s;
    __syncthreads();
    if (tid == 0) {
        float t = 0.0f;
#pragma unroll
        for (int j = 0; j < 8; j++) t += fsum[j];
        g_colsum[e] = t;
    }
}

// ---------------------------------------------------------------------------
// Kernel 3: load-balancing loss (scalar).
// ---------------------------------------------------------------------------
__global__ void loss_kernel(float* __restrict__ out_loss) {
    const int e = threadIdx.x;   // 64 threads
    __shared__ float sh[N_EXP];
    sh[e] = ((float)g_counts[e] / (float)(N_TOK * TOPK)) *
            (g_colsum[e] / (float)N_TOK);
    __syncthreads();
    if (e == 0) {
        float s = 0.0f;
#pragma unroll
        for (int j = 0; j < N_EXP; j++) s += sh[j];
        out_loss[0] = 0.01f * (float)N_EXP * s;
    }
}

// ---------------------------------------------------------------------------
extern "C" void kernel_launch(void* const* d_in, const int* in_sizes, int n_in,
                              void* d_out, int out_size) {
    const float* x  = (const float*)d_in[0];
    const float* gw = (const float*)d_in[1];
    if (n_in >= 2 && in_sizes[0] < in_sizes[1]) {  // robustness vs input ordering
        const float* t = x; x = gw; gw = t;
    }
    float* out = (float*)d_out;

    // layout: [dispatch_mask (N,E,C)] [combine_weights (N,E,C)] [probs (N,E)] [loss]
    float* mask    = out;
    float* combine = out + NEC;
    float* probs   = out + 2 * NEC;
    float* loss    = out + 2 * NEC + (size_t)N_TOK * N_EXP;

    static bool s_attr_done = false;
    if (!s_attr_done) {
        cudaFuncSetAttribute(gemm_topk_kernel,
                             cudaFuncAttributeMaxDynamicSharedMemorySize,
                             16384 * sizeof(float));
        s_attr_done = true;
    }

    // One-wave fused kernel: GEMM + hidden zero-fill of mask+combine.
    gemm_topk_kernel<<<GRID_TOTAL, 512, 16384 * sizeof(float)>>>(x, gw, probs, out);
    scan_scatter_kernel<<<N_EXP, 256>>>(mask, combine, probs);
    loss_kernel<<<1, N_EXP>>>(loss);
}

// round 10
// speedup vs baseline: 2.4749x; 2.4749x over previous
#include <cuda_runtime.h>
#include <cstdint>

// Problem constants
#define N_TOK   8192
#define DIM     4096
#define N_EXP   64
#define TOPK    2
#define CAP     160           // ceil(1.25 * 8192 / 64)
#define NEC     ((size_t)N_TOK * N_EXP * CAP)   // 83,886,080

// Scratch (device globals; no allocation allowed)
__device__ int   g_topk_idx[N_TOK * TOPK];
__device__ float g_topk_val[N_TOK * TOPK];
__device__ int   g_counts[N_EXP];
__device__ float g_colsum[N_EXP];

// packed fp32x2 FMA (sm_103a FFMA2): d.lo += a.lo*b.lo, d.hi += a.hi*b.hi
__device__ __forceinline__ void fma2(unsigned long long& d,
                                     unsigned long long a,
                                     unsigned long long b) {
    asm("fma.rn.f32x2 %0, %1, %2, %0;" : "+l"(d) : "l"(a), "l"(b));
}
__device__ __forceinline__ float ull_lo(unsigned long long a) {
    return __uint_as_float((unsigned)(a & 0xffffffffu));
}
__device__ __forceinline__ float ull_hi(unsigned long long a) {
    return __uint_as_float((unsigned)(a >> 32));
}

// ---------------------------------------------------------------------------
// Kernel 1: GEMM (logits = x @ gate_w^T) + softmax + top-2, with the zero-
// fill of this block's 64-token slab of mask+combine (2 x 64x64x160 floats =
// 327,680 float4) interleaved into the K loop: 10 coalesced float4 zero
// stores per thread per chunk, K chunks 0..63 zero the mask slab, 64..127
// the combine slab. All 128 blocks participate -> full-chip write bandwidth
// hidden under the crossbar-bound GEMM (DRAM was at 8.9%).
// GEMM config is the proven R2 one: 256 thr, 64x64 tile, thread tile 8x2.
// ---------------------------------------------------------------------------
__global__ __launch_bounds__(256)
void gemm_topk_kernel(const float* __restrict__ x,
                      const float* __restrict__ gw,
                      float* __restrict__ probs_out,
                      float* __restrict__ zero_base) {
    __shared__ float smem[64 * 66];      // reused: Xs(2048)+Ws(2048) then logits

    float* Xs = smem;                    // [row][k] 64x32, swizzled by (row>>3)&7
    float* Ws = smem + 2048;             // [exp][k] 64x32, swizzled by exp&7

    const int tid = threadIdx.x;
    const int rowBase = blockIdx.x * 64;

    const int rg = tid & 7;              // 8 row-groups of 8 rows
    const int cg = tid >> 3;             // 32 col-groups of 2 cols
    const int c0 = cg * 2, c1 = c0 + 1;
    const int row0 = rg * 8;
    const int xswz = rg << 2;

    // staging indices (2 float4 of X and W per thread per chunk)
    const int fA = tid, fB = tid + 256;
    const int rA = fA >> 3, kA = (fA & 7) * 4;
    const int rB = fB >> 3, kB = (fB & 7) * 4;
    const int xsA = (rA * 32 + kA) ^ (((rA >> 3) & 7) << 2);
    const int xsB = (rB * 32 + kB) ^ (((rB >> 3) & 7) << 2);
    const int wsA = (rA * 32 + kA) ^ ((rA & 7) << 2);
    const int wsB = (rB * 32 + kB) ^ ((rB & 7) << 2);

    const float* xg = x + (size_t)rowBase * DIM;

    // zero-fill slab pointers: mask slab + combine slab for this block's tokens
    // (10240 floats per token per array = 2560 float4)
    float4* const zm4 = (float4*)zero_base + (size_t)rowBase * 2560;
    float4* const zc4 = (float4*)(zero_base + NEC) + (size_t)rowBase * 2560;
    const float4 z4 = make_float4(0.f, 0.f, 0.f, 0.f);

    unsigned long long acc[8][2];
#pragma unroll
    for (int r = 0; r < 8; r++) { acc[r][0] = 0ull; acc[r][1] = 0ull; }

    float4 xr0, xr1, wr0, wr1;
    xr0 = *(const float4*)&xg[(size_t)rA * DIM + kA];
    xr1 = *(const float4*)&xg[(size_t)rB * DIM + kB];
    wr0 = *(const float4*)&gw[(size_t)rA * DIM + kA];
    wr1 = *(const float4*)&gw[(size_t)rB * DIM + kB];

#pragma unroll 1
    for (int kc = 0; kc < DIM / 32; kc++) {
        *(float4*)&Xs[xsA] = xr0;
        *(float4*)&Xs[xsB] = xr1;
        *(float4*)&Ws[wsA] = wr0;
        *(float4*)&Ws[wsB] = wr1;
        __syncthreads();

        if (kc + 1 < DIM / 32) {
            const int ko = (kc + 1) * 32;
            xr0 = *(const float4*)&xg[(size_t)rA * DIM + ko + kA];
            xr1 = *(const float4*)&xg[(size_t)rB * DIM + ko + kB];
            wr0 = *(const float4*)&gw[(size_t)rA * DIM + ko + kA];
            wr1 = *(const float4*)&gw[(size_t)rB * DIM + ko + kB];
        }

        // interleaved zero-fill: 10 independent coalesced stores (fire & forget)
        {
            float4* zp = (kc < 64) ? (zm4 + (size_t)kc * 2560)
                                   : (zc4 + (size_t)(kc - 64) * 2560);
#pragma unroll
            for (int j = 0; j < 10; j++)
                zp[j * 256 + tid] = z4;
        }

#pragma unroll
        for (int k = 0; k < 32; k += 4) {
            ulonglong2 B0 = *(const ulonglong2*)&Ws[(c0 * 32 + k) ^ ((c0 & 7) << 2)];
            ulonglong2 B1 = *(const ulonglong2*)&Ws[(c1 * 32 + k) ^ ((c1 & 7) << 2)];
#pragma unroll
            for (int r = 0; r < 8; r++) {
                ulonglong2 A = *(const ulonglong2*)&Xs[((row0 + r) * 32 + k) ^ xswz];
                fma2(acc[r][0], A.x, B0.x);
                fma2(acc[r][0], A.y, B0.y);
                fma2(acc[r][1], A.x, B1.x);
                fma2(acc[r][1], A.y, B1.y);
            }
        }
        __syncthreads();
    }

    // write logits to smem (stride 66 to dodge bank conflicts)
    float* lg = smem;
#pragma unroll
    for (int r = 0; r < 8; r++) {
        lg[(row0 + r) * 66 + c0] = ull_lo(acc[r][0]) + ull_hi(acc[r][0]);
        lg[(row0 + r) * 66 + c1] = ull_lo(acc[r][1]) + ull_hi(acc[r][1]);
    }
    __syncthreads();

    // per-row softmax + top-2: warp w handles rows w*8 .. w*8+7
    const int lane = tid & 31;
    const int w = tid >> 5;
    for (int rr = 0; rr < 8; rr++) {
        const int r = w * 8 + rr;
        float2 lv = *(float2*)&lg[r * 66 + lane * 2];
        float v0 = lv.x, v1 = lv.y;

        float m = fmaxf(v0, v1);
#pragma unroll
        for (int off = 16; off; off >>= 1)
            m = fmaxf(m, __shfl_xor_sync(0xffffffffu, m, off));

        float e0 = expf(v0 - m), e1 = expf(v1 - m);
        float s = e0 + e1;
#pragma unroll
        for (int off = 16; off; off >>= 1)
            s += __shfl_xor_sync(0xffffffffu, s, off);
        float inv = 1.0f / s;

        const int gtok = rowBase + r;
        *(float2*)&probs_out[(size_t)gtok * N_EXP + lane * 2] =
            make_float2(e0 * inv, e1 * inv);

        // top-1 (ties -> lower index, matching jax top_k)
        float cv; int ci;
        if (v0 >= v1) { cv = v0; ci = lane * 2; } else { cv = v1; ci = lane * 2 + 1; }
#pragma unroll
        for (int off = 16; off; off >>= 1) {
            float ov = __shfl_xor_sync(0xffffffffu, cv, off);
            int   oi = __shfl_xor_sync(0xffffffffu, ci, off);
            if (ov > cv || (ov == cv && oi < ci)) { cv = ov; ci = oi; }
        }
        const float t1v = cv; const int t1i = ci;

        // top-2: lane holding t1i offers its other column
        if (lane * 2 == t1i)          { cv = v1; ci = lane * 2 + 1; }
        else if (lane * 2 + 1 == t1i) { cv = v0; ci = lane * 2; }
        else if (v0 >= v1)            { cv = v0; ci = lane * 2; }
        else                          { cv = v1; ci = lane * 2 + 1; }
#pragma unroll
        for (int off = 16; off; off >>= 1) {
            float ov = __shfl_xor_sync(0xffffffffu, cv, off);
            int   oi = __shfl_xor_sync(0xffffffffu, ci, off);
            if (ov > cv || (ov == cv && oi < ci)) { cv = ov; ci = oi; }
        }
        const float t2v = cv; const int t2i = ci;

        if (lane == 0) {
            float rr2 = expf(t2v - t1v);
            float inv2 = 1.0f / (1.0f + rr2);
            g_topk_idx[2 * gtok]     = t1i;
            g_topk_idx[2 * gtok + 1] = t2i;
            g_topk_val[2 * gtok]     = inv2;
            g_topk_val[2 * gtok + 1] = rr2 * inv2;
        }
    }
}

// ---------------------------------------------------------------------------
// Kernel 2: one block per expert. Ordered prefix count over the flat (N*K)
// assignment list (token-major, matching reference cumsum), scatter kept
// entries (overwrites the zeros written by kernel 1 — ordered by the kernel
// boundary), record total count, deterministic column-sum of probs.
// ---------------------------------------------------------------------------
__global__ __launch_bounds__(256)
void scan_scatter_kernel(float* __restrict__ mask,
                         float* __restrict__ combine,
                         const float* __restrict__ probs) {
    const int e = blockIdx.x;
    const int tid = threadIdx.x;
    const int lane = tid & 31;
    const int w = tid >> 5;
    __shared__ int   wsum[8];
    __shared__ float fsum[8];

    int running = 0;
    for (int base = 0; base < N_TOK * TOPK; base += 256) {
        const int i = base + tid;
        const bool m = (g_topk_idx[i] == e);
        const unsigned bal = __ballot_sync(0xffffffffu, m);
        if (lane == 0) wsum[w] = __popc(bal);
        __syncthreads();
        int woff = 0, tot = 0;
#pragma unroll
        for (int j = 0; j < 8; j++) {
            int t = wsum[j];
            if (j < w) woff += t;
            tot += t;
        }
        if (m) {
            const int slot = running + woff + __popc(bal & ((1u << lane) - 1u));
            if (slot < CAP) {
                const int tok = i >> 1;
                const size_t o = (size_t)tok * (N_EXP * CAP) + e * CAP + slot;
                mask[o] = 1.0f;
                combine[o] = g_topk_val[i];
            }
        }
        running += tot;
        __syncthreads();
    }
    if (tid == 0) g_counts[e] = running;

    // deterministic column sum of probs[:, e]
    float s = 0.0f;
    for (int t = tid; t < N_TOK; t += 256)
        s += probs[(size_t)t * N_EXP + e];
#pragma unroll
    for (int off = 16; off; off >>= 1)
        s += __shfl_xor_sync(0xffffffffu, s, off);
    if (lane == 0) fsum[w] = s;
    __syncthreads();
    if (tid == 0) {
        float t = 0.0f;
#pragma unroll
        for (int j = 0; j < 8; j++) t += fsum[j];
        g_colsum[e] = t;
    }
}

// ---------------------------------------------------------------------------
// Kernel 3: load-balancing loss (scalar).
// ---------------------------------------------------------------------------
__global__ void loss_kernel(float* __restrict__ out_loss) {
    const int e = threadIdx.x;   // 64 threads
    __shared__ float sh[N_EXP];
    sh[e] = ((float)g_counts[e] / (float)(N_TOK * TOPK)) *
            (g_colsum[e] / (float)N_TOK);
    __syncthreads();
    if (e == 0) {
        float s = 0.0f;
#pragma unroll
        for (int j = 0; j < N_EXP; j++) s += sh[j];
        out_loss[0] = 0.01f * (float)N_EXP * s;
    }
}

// ---------------------------------------------------------------------------
extern "C" void kernel_launch(void* const* d_in, const int* in_sizes, int n_in,
                              void* d_out, int out_size) {
    const float* x  = (const float*)d_in[0];
    const float* gw = (const float*)d_in[1];
    if (n_in >= 2 && in_sizes[0] < in_sizes[1]) {  // robustness vs input ordering
        const float* t = x; x = gw; gw = t;
    }
    float* out = (float*)d_out;

    // layout: [dispatch_mask (N,E,C)] [combine_weights (N,E,C)] [probs (N,E)] [loss]
    float* mask    = out;
    float* combine = out + NEC;
    float* probs   = out + 2 * NEC;
    float* loss    = out + 2 * NEC + (size_t)N_TOK * N_EXP;

    // No memset: kernel 1 zero-fills mask+combine interleaved with the GEMM.
    gemm_topk_kernel<<<N_TOK / 64, 256>>>(x, gw, probs, out);
    scan_scatter_kernel<<<N_EXP, 256>>>(mask, combine, probs);
    loss_kernel<<<1, N_EXP>>>(loss);
}

// round 12
// speedup vs baseline: 2.8063x; 1.1339x over previous
#include <cuda_runtime.h>
#include <cstdint>

// Problem constants
#define N_TOK   8192
#define DIM     4096
#define N_EXP   64
#define TOPK    2
#define CAP     160           // ceil(1.25 * 8192 / 64)
#define NEC     ((size_t)N_TOK * N_EXP * CAP)   // 83,886,080

// Scratch (device globals; no allocation allowed)
__device__ float g_logits_part[2][N_TOK * N_EXP];   // 4MB split-K partials
__device__ int   g_topk_idx[N_TOK * TOPK];
__device__ float g_topk_val[N_TOK * TOPK];
__device__ int   g_counts[N_EXP];
__device__ float g_colsum[N_EXP];

// packed fp32x2 FMA (sm_103a FFMA2): d.lo += a.lo*b.lo, d.hi += a.hi*b.hi
__device__ __forceinline__ void fma2(unsigned long long& d,
                                     unsigned long long a,
                                     unsigned long long b) {
    asm("fma.rn.f32x2 %0, %1, %2, %0;" : "+l"(d) : "l"(a), "l"(b));
}
__device__ __forceinline__ float ull_lo(unsigned long long a) {
    return __uint_as_float((unsigned)(a & 0xffffffffu));
}
__device__ __forceinline__ float ull_hi(unsigned long long a) {
    return __uint_as_float((unsigned)(a >> 32));
}

// ---------------------------------------------------------------------------
// Kernel 1: split-K GEMM partial + interleaved zero-fill.
// Grid 256 x 256 threads, __launch_bounds__(256,2) -> 2 CTAs/SM (16 warps/SM).
// Block b: rows (b>>1)*64 .. +63, K half (b&1)*2048 .. +2047 (64 chunks of 32).
// Thread tile 4x4 with broadcast-friendly mapping (rg=tid>>4 rows, cg=tid&15
// cols cg+{0,16,32,48}): A-LDS.128 = half-warp broadcast (1-2 crossbar cyc),
// B-LDS.128 = 16 distinct addrs (2 cyc). Crossbar 96 cyc/CTA/k4 < fma 128 ->
// fma-bound at 2 CTAs/SM. Partial logits to g_logits_part[kHalf].
// Zero-fill: kHalf=0 zeroes the block's mask slab, kHalf=1 its combine slab
// (2560 float4 per chunk, 10 per thread, coalesced), hidden under compute.
// ---------------------------------------------------------------------------
__global__ __launch_bounds__(256, 2)
void gemm_partial_kernel(const float* __restrict__ x,
                         const float* __restrict__ gw,
                         float* __restrict__ zero_base) {
    __shared__ float smem[8192];         // 32KB: two buffers of (X 2048 | W 2048)

    const int tid = threadIdx.x;
    const int rowBase = (blockIdx.x >> 1) * 64;
    const int kHalf = blockIdx.x & 1;

    const int rg = tid >> 4;             // 0..15 -> rows rg*4 .. rg*4+3
    const int cg = tid & 15;             // cols cg, cg+16, cg+32, cg+48
    const int row0 = rg * 4;
    const int swzA = (rg & 7) << 2;      // ((row>>2)&7)<<2 for rows row0..+3
    const int swzB = (cg & 7) << 2;      // (col&7)<<2 for all 4 cols

    const float* xg = x + (size_t)rowBase * DIM + kHalf * 2048;
    const float* wg = gw + kHalf * 2048;

    // staging: 2 float4 per thread per matrix per chunk (512 float4 each)
    int xoff[2], woff[2], gidx[2];
#pragma unroll
    for (int j = 0; j < 2; j++) {
        const int f = tid + j * 256;     // 0..511
        const int r = f >> 3;            // row/expert 0..63
        const int kq = (f & 7) * 4;      // float offset in 32-float row
        xoff[j] = (r * 32 + kq) ^ (((r >> 2) & 7) << 2);  // A swizzle
        woff[j] = (r * 32 + kq) ^ ((r & 7) << 2);         // B swizzle
        gidx[j] = r * DIM + kq;
    }

    // zero-fill slab: this block's 64 tokens of (kHalf? combine : mask)
    // 64 chunks x 2560 float4 = 163,840 float4
    float4* const zslab = (float4*)(zero_base + (size_t)kHalf * NEC)
                          + (size_t)rowBase * 2560;
    const float4 z4 = make_float4(0.f, 0.f, 0.f, 0.f);

    unsigned long long acc[4][4];
#pragma unroll
    for (int r = 0; r < 4; r++)
#pragma unroll
        for (int c = 0; c < 4; c++) acc[r][c] = 0ull;

    float4 xr[2], wr[2];
#pragma unroll
    for (int j = 0; j < 2; j++) {        // prologue: chunk 0 of this half
        xr[j] = *(const float4*)&xg[gidx[j]];
        wr[j] = *(const float4*)&wg[gidx[j]];
    }

#pragma unroll 1
    for (int kc = 0; kc < 64; kc++) {
        float* Xb = smem + (kc & 1) * 4096;
        float* Wb = Xb + 2048;
#pragma unroll
        for (int j = 0; j < 2; j++) {
            *(float4*)&Xb[xoff[j]] = xr[j];
            *(float4*)&Wb[woff[j]] = wr[j];
        }
        __syncthreads();

        if (kc < 63) {
            const float* xp = xg + (kc + 1) * 32;
            const float* wp = wg + (kc + 1) * 32;
#pragma unroll
            for (int j = 0; j < 2; j++) {
                xr[j] = *(const float4*)&xp[gidx[j]];
                wr[j] = *(const float4*)&wp[gidx[j]];
            }
        }

        // interleaved zero-fill: 10 coalesced fire-and-forget stores
        {
            float4* zp = zslab + (size_t)kc * 2560;
#pragma unroll
            for (int j = 0; j < 10; j++)
                zp[j * 256 + tid] = z4;
        }

#pragma unroll
        for (int k = 0; k < 32; k += 4) {
            // B: 16 distinct 16B addrs/warp (2-way lane pairing) -> 2 cyc
            ulonglong2 B0 = *(const ulonglong2*)&Wb[((cg +  0) * 32 + k) ^ swzB];
            ulonglong2 B1 = *(const ulonglong2*)&Wb[((cg + 16) * 32 + k) ^ swzB];
            ulonglong2 B2 = *(const ulonglong2*)&Wb[((cg + 32) * 32 + k) ^ swzB];
            ulonglong2 B3 = *(const ulonglong2*)&Wb[((cg + 48) * 32 + k) ^ swzB];
#pragma unroll
            for (int r = 0; r < 4; r++) {
                // A: half-warp broadcast, 2 distinct addrs -> 1-2 cyc
                ulonglong2 A = *(const ulonglong2*)&Xb[((row0 + r) * 32 + k) ^ swzA];
                fma2(acc[r][0], A.x, B0.x); fma2(acc[r][0], A.y, B0.y);
                fma2(acc[r][1], A.x, B1.x); fma2(acc[r][1], A.y, B1.y);
                fma2(acc[r][2], A.x, B2.x); fma2(acc[r][2], A.y, B2.y);
                fma2(acc[r][3], A.x, B3.x); fma2(acc[r][3], A.y, B3.y);
            }
        }
        // next iteration's stores hit the other buffer; the top-of-loop
        // barrier proves all reads of that buffer completed.
    }

    // epilogue: write 16 partial logits (no barrier needed; accs in regs)
    float* lp = g_logits_part[kHalf];
#pragma unroll
    for (int r = 0; r < 4; r++)
#pragma unroll
        for (int c = 0; c < 4; c++)
            lp[(size_t)(rowBase + row0 + r) * N_EXP + cg + c * 16] =
                ull_lo(acc[r][c]) + ull_hi(acc[r][c]);
}

// ---------------------------------------------------------------------------
// Kernel 2: combine the two K-half partials (exactly 2 adds per logit ->
// deterministic), softmax -> probs, top-2 -> g_topk. One warp per token.
// Grid 1024 x 256 (8 tokens/block).
// ---------------------------------------------------------------------------
__global__ __launch_bounds__(256)
void softmax_topk_kernel(float* __restrict__ probs_out) {
    const int lane = threadIdx.x & 31;
    const int w = threadIdx.x >> 5;
    const int tok = blockIdx.x * 8 + w;

    float2 a = *(float2*)&g_logits_part[0][(size_t)tok * N_EXP + lane * 2];
    float2 b = *(float2*)&g_logits_part[1][(size_t)tok * N_EXP + lane * 2];
    float v0 = a.x + b.x, v1 = a.y + b.y;

    float m = fmaxf(v0, v1);
#pragma unroll
    for (int off = 16; off; off >>= 1)
        m = fmaxf(m, __shfl_xor_sync(0xffffffffu, m, off));

    float e0 = expf(v0 - m), e1 = expf(v1 - m);
    float s = e0 + e1;
#pragma unroll
    for (int off = 16; off; off >>= 1)
        s += __shfl_xor_sync(0xffffffffu, s, off);
    float inv = 1.0f / s;

    *(float2*)&probs_out[(size_t)tok * N_EXP + lane * 2] =
        make_float2(e0 * inv, e1 * inv);

    // top-1 (ties -> lower index, matching jax top_k)
    float cv; int ci;
    if (v0 >= v1) { cv = v0; ci = lane * 2; } else { cv = v1; ci = lane * 2 + 1; }
#pragma unroll
    for (int off = 16; off; off >>= 1) {
        float ov = __shfl_xor_sync(0xffffffffu, cv, off);
        int   oi = __shfl_xor_sync(0xffffffffu, ci, off);
        if (ov > cv || (ov == cv && oi < ci)) { cv = ov; ci = oi; }
    }
    const float t1v = cv; const int t1i = ci;

    // top-2: lane holding t1i offers its other column
    if (lane * 2 == t1i)          { cv = v1; ci = lane * 2 + 1; }
    else if (lane * 2 + 1 == t1i) { cv = v0; ci = lane * 2; }
    else if (v0 >= v1)            { cv = v0; ci = lane * 2; }
    else                          { cv = v1; ci = lane * 2 + 1; }
#pragma unroll
    for (int off = 16; off; off >>= 1) {
        float ov = __shfl_xor_sync(0xffffffffu, cv, off);
        int   oi = __shfl_xor_sync(0xffffffffu, ci, off);
        if (ov > cv || (ov == cv && oi < ci)) { cv = ov; ci = oi; }
    }
    const float t2v = cv; const int t2i = ci;

    if (lane == 0) {
        float rr2 = expf(t2v - t1v);
        float inv2 = 1.0f / (1.0f + rr2);
        g_topk_idx[2 * tok]     = t1i;
        g_topk_idx[2 * tok + 1] = t2i;
        g_topk_val[2 * tok]     = inv2;
        g_topk_val[2 * tok + 1] = rr2 * inv2;
    }
}

// ---------------------------------------------------------------------------
// Kernel 3: one block per expert. Ordered prefix count over the flat (N*K)
// assignment list (token-major, matching reference cumsum), scatter kept
// entries (overwrites the zeros written by kernel 1 — ordered by kernel
// boundaries), record total count, deterministic column-sum of probs.
// ---------------------------------------------------------------------------
__global__ __launch_bounds__(256)
void scan_scatter_kernel(float* __restrict__ mask,
                         float* __restrict__ combine,
                         const float* __restrict__ probs) {
    const int e = blockIdx.x;
    const int tid = threadIdx.x;
    const int lane = tid & 31;
    const int w = tid >> 5;
    __shared__ int   wsum[8];
    __shared__ float fsum[8];

    int running = 0;
    for (int base = 0; base < N_TOK * TOPK; base += 256) {
        const int i = base + tid;
        const bool m = (g_topk_idx[i] == e);
        const unsigned bal = __ballot_sync(0xffffffffu, m);
        if (lane == 0) wsum[w] = __popc(bal);
        __syncthreads();
        int woff = 0, tot = 0;
#pragma unroll
        for (int j = 0; j < 8; j++) {
            int t = wsum[j];
            if (j < w) woff += t;
            tot += t;
        }
        if (m) {
            const int slot = running + woff + __popc(bal & ((1u << lane) - 1u));
            if (slot < CAP) {
                const int tok = i >> 1;
                const size_t o = (size_t)tok * (N_EXP * CAP) + e * CAP + slot;
                mask[o] = 1.0f;
                combine[o] = g_topk_val[i];
            }
        }
        running += tot;
        __syncthreads();
    }
    if (tid == 0) g_counts[e] = running;

    // deterministic column sum of probs[:, e]
    float s = 0.0f;
    for (int t = tid; t < N_TOK; t += 256)
        s += probs[(size_t)t * N_EXP + e];
#pragma unroll
    for (int off = 16; off; off >>= 1)
        s += __shfl_xor_sync(0xffffffffu, s, off);
    if (lane == 0) fsum[w] = s;
    __syncthreads();
    if (tid == 0) {
        float t = 0.0f;
#pragma unroll
        for (int j = 0; j < 8; j++) t += fsum[j];
        g_colsum[e] = t;
    }
}

// ---------------------------------------------------------------------------
// Kernel 4: load-balancing loss (scalar).
// ---------------------------------------------------------------------------
__global__ void loss_kernel(float* __restrict__ out_loss) {
    const int e = threadIdx.x;   // 64 threads
    __shared__ float sh[N_EXP];
    sh[e] = ((float)g_counts[e] / (float)(N_TOK * TOPK)) *
            (g_colsum[e] / (float)N_TOK);
    __syncthreads();
    if (e == 0) {
        float s = 0.0f;
#pragma unroll
        for (int j = 0; j < N_EXP; j++) s += sh[j];
        out_loss[0] = 0.01f * (float)N_EXP * s;
    }
}

// ---------------------------------------------------------------------------
extern "C" void kernel_launch(void* const* d_in, const int* in_sizes, int n_in,
                              void* d_out, int out_size) {
    const float* x  = (const float*)d_in[0];
    const float* gw = (const float*)d_in[1];
    if (n_in >= 2 && in_sizes[0] < in_sizes[1]) {  // robustness vs input ordering
        const float* t = x; x = gw; gw = t;
    }
    float* out = (float*)d_out;

    // layout: [dispatch_mask (N,E,C)] [combine_weights (N,E,C)] [probs (N,E)] [loss]
    float* mask    = out;
    float* combine = out + NEC;
    float* probs   = out + 2 * NEC;
    float* loss    = out + 2 * NEC + (size_t)N_TOK * N_EXP;

    // Split-K GEMM (zero-fill fused) -> combine/softmax/top2 -> scan -> loss.
    gemm_partial_kernel<<<2 * (N_TOK / 64), 256>>>(x, gw, out);
    softmax_topk_kernel<<<N_TOK / 8, 256>>>(probs);
    scan_scatter_kernel<<<N_EXP, 256>>>(mask, combine, probs);
    loss_kernel<<<1, N_EXP>>>(loss);
}

// round 14
// speedup vs baseline: 3.1773x; 1.1322x over previous
#include <cuda_runtime.h>
#include <cstdint>

// Problem constants
#define N_TOK   8192
#define DIM     4096
#define N_EXP   64
#define TOPK    2
#define CAP     160           // ceil(1.25 * 8192 / 64)
#define NEC     ((size_t)N_TOK * N_EXP * CAP)   // 83,886,080

// Scratch (device globals; no allocation allowed)
__device__ float g_logits_part[2][N_TOK * N_EXP];   // 4MB split-K partials
__device__ int   g_topk_idx[N_TOK * TOPK];
__device__ float g_topk_val[N_TOK * TOPK];
__device__ int   g_counts[N_EXP];
__device__ float g_colsum[N_EXP];

// packed fp32x2 FMA (sm_103a FFMA2): d.lo += a.lo*b.lo, d.hi += a.hi*b.hi
__device__ __forceinline__ void fma2(unsigned long long& d,
                                     unsigned long long a,
                                     unsigned long long b) {
    asm("fma.rn.f32x2 %0, %1, %2, %0;" : "+l"(d) : "l"(a), "l"(b));
}
__device__ __forceinline__ float ull_lo(unsigned long long a) {
    return __uint_as_float((unsigned)(a & 0xffffffffu));
}
__device__ __forceinline__ float ull_hi(unsigned long long a) {
    return __uint_as_float((unsigned)(a >> 32));
}
__device__ __forceinline__ uint32_t smem_u32(const void* p) {
    uint32_t a;
    asm("{ .reg .u64 t; cvta.to.shared.u64 t, %1; cvt.u32.u64 %0, t; }"
        : "=r"(a) : "l"(p));
    return a;
}

// ---------------------------------------------------------------------------
// Kernel 1: split-K GEMM partial + TMA-bulk zero-fill.
// Grid 256 x 256 threads, __launch_bounds__(256,2) -> 2 CTAs/SM (16 warps/SM).
// Block b: rows (b>>1)*64 .. +63, K half (b&1)*2048 .. +2047 (64 chunks of 32).
// Thread tile 4x4 with broadcast-friendly LDS mapping (fma-bound inner loop).
// Zero-fill of the block's contiguous 2.62MB output slab (kHalf=0: mask,
// kHalf=1: combine) goes through cp.async.bulk S2G (5 x 8KB per chunk from an
// 8KB zeroed smem staging buffer) instead of 80 warp-STG.128/chunk — removing
// ~1920 cyc/chunk of STG issue from the LSU path. In-flight bulk groups are
// BOUNDED at 8 via wait_group inside the loop (defensive vs queue overflow).
// ---------------------------------------------------------------------------
__global__ __launch_bounds__(256, 2)
void gemm_partial_kernel(const float* __restrict__ x,
                         const float* __restrict__ gw,
                         float* __restrict__ zero_base) {
    __shared__ __align__(128) float smem[8192 + 2048];  // 40KB: dbuf + zero staging
    float* const zbuf = smem + 8192;                    // 8KB of zeros

    const int tid = threadIdx.x;
    const int rowBase = (blockIdx.x >> 1) * 64;
    const int kHalf = blockIdx.x & 1;

    const int rg = tid >> 4;             // 0..15 -> rows rg*4 .. rg*4+3
    const int cg = tid & 15;             // cols cg, cg+16, cg+32, cg+48
    const int row0 = rg * 4;
    const int swzA = (rg & 7) << 2;      // ((row>>2)&7)<<2 for rows row0..+3
    const int swzB = (cg & 7) << 2;      // (col&7)<<2 for all 4 cols

    const float* xg = x + (size_t)rowBase * DIM + kHalf * 2048;
    const float* wg = gw + kHalf * 2048;

    // init zero staging buffer (2048 floats = 512 float4)
    const float4 z4 = make_float4(0.f, 0.f, 0.f, 0.f);
    *(float4*)&zbuf[tid * 4] = z4;
    *(float4*)&zbuf[(tid + 256) * 4] = z4;
    asm volatile("fence.proxy.async.shared::cta;" ::: "memory");

    // staging: 2 float4 per thread per matrix per chunk (512 float4 each)
    int xoff[2], woff[2], gidx[2];
#pragma unroll
    for (int j = 0; j < 2; j++) {
        const int f = tid + j * 256;     // 0..511
        const int r = f >> 3;            // row/expert 0..63
        const int kq = (f & 7) * 4;      // float offset in 32-float row
        xoff[j] = (r * 32 + kq) ^ (((r >> 2) & 7) << 2);  // A swizzle
        woff[j] = (r * 32 + kq) ^ ((r & 7) << 2);         // B swizzle
        gidx[j] = r * DIM + kq;
    }

    // this block's contiguous output slab: 64 tokens * 64 exp * 160 floats
    char* const slab = (char*)(zero_base + (size_t)kHalf * NEC
                               + (size_t)rowBase * (N_EXP * CAP));
    const uint32_t zsrc = smem_u32(zbuf);

    unsigned long long acc[4][4];
#pragma unroll
    for (int r = 0; r < 4; r++)
#pragma unroll
        for (int c = 0; c < 4; c++) acc[r][c] = 0ull;

    float4 xr[2], wr[2];
#pragma unroll
    for (int j = 0; j < 2; j++) {        // prologue: chunk 0 of this half
        xr[j] = *(const float4*)&xg[gidx[j]];
        wr[j] = *(const float4*)&wg[gidx[j]];
    }

#pragma unroll 1
    for (int kc = 0; kc < 64; kc++) {
        float* Xb = smem + (kc & 1) * 4096;
        float* Wb = Xb + 2048;
#pragma unroll
        for (int j = 0; j < 2; j++) {
            *(float4*)&Xb[xoff[j]] = xr[j];
            *(float4*)&Wb[woff[j]] = wr[j];
        }
        __syncthreads();

        if (kc < 63) {
            const float* xp = xg + (kc + 1) * 32;
            const float* wp = wg + (kc + 1) * 32;
#pragma unroll
            for (int j = 0; j < 2; j++) {
                xr[j] = *(const float4*)&xp[gidx[j]];
                wr[j] = *(const float4*)&wp[gidx[j]];
            }
        }

        // zero-fill via TMA bulk stores: 5 x 8KB per chunk, issued by tid 0.
        // wait_group 8 bounds outstanding groups (no unbounded queue growth).
        if (tid == 0) {
            unsigned long long gdst =
                (unsigned long long)(slab + (size_t)kc * 40960);
#pragma unroll
            for (int j = 0; j < 5; j++) {
                asm volatile(
                    "cp.async.bulk.global.shared::cta.bulk_group [%0], [%1], %2;"
                    :: "l"(gdst + (unsigned long long)j * 8192),
                       "r"(zsrc), "r"(8192)
                    : "memory");
            }
            asm volatile("cp.async.bulk.commit_group;" ::: "memory");
            asm volatile("cp.async.bulk.wait_group 8;" ::: "memory");
        }

#pragma unroll
        for (int k = 0; k < 32; k += 4) {
            // B: 16 distinct 16B addrs/warp (2-way lane pairing) -> 2 cyc
            ulonglong2 B0 = *(const ulonglong2*)&Wb[((cg +  0) * 32 + k) ^ swzB];
            ulonglong2 B1 = *(const ulonglong2*)&Wb[((cg + 16) * 32 + k) ^ swzB];
            ulonglong2 B2 = *(const ulonglong2*)&Wb[((cg + 32) * 32 + k) ^ swzB];
            ulonglong2 B3 = *(const ulonglong2*)&Wb[((cg + 48) * 32 + k) ^ swzB];
#pragma unroll
            for (int r = 0; r < 4; r++) {
                // A: half-warp broadcast, 2 distinct addrs -> 1-2 cyc
                ulonglong2 A = *(const ulonglong2*)&Xb[((row0 + r) * 32 + k) ^ swzA];
                fma2(acc[r][0], A.x, B0.x); fma2(acc[r][0], A.y, B0.y);
                fma2(acc[r][1], A.x, B1.x); fma2(acc[r][1], A.y, B1.y);
                fma2(acc[r][2], A.x, B2.x); fma2(acc[r][2], A.y, B2.y);
                fma2(acc[r][3], A.x, B3.x); fma2(acc[r][3], A.y, B3.y);
            }
        }
        // next iteration's stores hit the other buffer; the top-of-loop
        // barrier proves all reads of that buffer completed.
    }

    // epilogue: write 16 partial logits (accs in regs, no barrier needed)
    float* lp = g_logits_part[kHalf];
#pragma unroll
    for (int r = 0; r < 4; r++)
#pragma unroll
        for (int c = 0; c < 4; c++)
            lp[(size_t)(rowBase + row0 + r) * N_EXP + cg + c * 16] =
                ull_lo(acc[r][c]) + ull_hi(acc[r][c]);

    // drain all outstanding bulk stores before kernel end (orders them
    // ahead of scan_scatter's overwrites via the kernel boundary)
    if (tid == 0)
        asm volatile("cp.async.bulk.wait_group 0;" ::: "memory");
}

// ---------------------------------------------------------------------------
// Kernel 2: combine the two K-half partials (exactly 2 adds per logit ->
// deterministic), softmax -> probs, top-2 -> g_topk. One warp per token.
// ---------------------------------------------------------------------------
__global__ __launch_bounds__(256)
void softmax_topk_kernel(float* __restrict__ probs_out) {
    const int lane = threadIdx.x & 31;
    const int w = threadIdx.x >> 5;
    const int tok = blockIdx.x * 8 + w;

    float2 a = *(float2*)&g_logits_part[0][(size_t)tok * N_EXP + lane * 2];
    float2 b = *(float2*)&g_logits_part[1][(size_t)tok * N_EXP + lane * 2];
    float v0 = a.x + b.x, v1 = a.y + b.y;

    float m = fmaxf(v0, v1);
#pragma unroll
    for (int off = 16; off; off >>= 1)
        m = fmaxf(m, __shfl_xor_sync(0xffffffffu, m, off));

    float e0 = expf(v0 - m), e1 = expf(v1 - m);
    float s = e0 + e1;
#pragma unroll
    for (int off = 16; off; off >>= 1)
        s += __shfl_xor_sync(0xffffffffu, s, off);
    float inv = 1.0f / s;

    *(float2*)&probs_out[(size_t)tok * N_EXP + lane * 2] =
        make_float2(e0 * inv, e1 * inv);

    // top-1 (ties -> lower index, matching jax top_k)
    float cv; int ci;
    if (v0 >= v1) { cv = v0; ci = lane * 2; } else { cv = v1; ci = lane * 2 + 1; }
#pragma unroll
    for (int off = 16; off; off >>= 1) {
        float ov = __shfl_xor_sync(0xffffffffu, cv, off);
        int   oi = __shfl_xor_sync(0xffffffffu, ci, off);
        if (ov > cv || (ov == cv && oi < ci)) { cv = ov; ci = oi; }
    }
    const float t1v = cv; const int t1i = ci;

    // top-2: lane holding t1i offers its other column
    if (lane * 2 == t1i)          { cv = v1; ci = lane * 2 + 1; }
    else if (lane * 2 + 1 == t1i) { cv = v0; ci = lane * 2; }
    else if (v0 >= v1)            { cv = v0; ci = lane * 2; }
    else                          { cv = v1; ci = lane * 2 + 1; }
#pragma unroll
    for (int off = 16; off; off >>= 1) {
        float ov = __shfl_xor_sync(0xffffffffu, cv, off);
        int   oi = __shfl_xor_sync(0xffffffffu, ci, off);
        if (ov > cv || (ov == cv && oi < ci)) { cv = ov; ci = oi; }
    }
    const float t2v = cv; const int t2i = ci;

    if (lane == 0) {
        float rr2 = expf(t2v - t1v);
        float inv2 = 1.0f / (1.0f + rr2);
        g_topk_idx[2 * tok]     = t1i;
        g_topk_idx[2 * tok + 1] = t2i;
        g_topk_val[2 * tok]     = inv2;
        g_topk_val[2 * tok + 1] = rr2 * inv2;
    }
}

// ---------------------------------------------------------------------------
// Kernel 3: one block per expert. Ordered prefix count over the flat (N*K)
// assignment list (token-major, matching reference cumsum), scatter kept
// entries (overwrites zeros from kernel 1 — ordered by kernel boundaries),
// record total count, deterministic column-sum of probs.
// ---------------------------------------------------------------------------
__global__ __launch_bounds__(256)
void scan_scatter_kernel(float* __restrict__ mask,
                         float* __restrict__ combine,
                         const float* __restrict__ probs) {
    const int e = blockIdx.x;
    const int tid = threadIdx.x;
    const int lane = tid & 31;
    const int w = tid >> 5;
    __shared__ int   wsum[8];
    __shared__ float fsum[8];

    int running = 0;
    for (int base = 0; base < N_TOK * TOPK; base += 256) {
        const int i = base + tid;
        const bool m = (g_topk_idx[i] == e);
        const unsigned bal = __ballot_sync(0xffffffffu, m);
        if (lane == 0) wsum[w] = __popc(bal);
        __syncthreads();
        int woff = 0, tot = 0;
#pragma unroll
        for (int j = 0; j < 8; j++) {
            int t = wsum[j];
            if (j < w) woff += t;
            tot += t;
        }
        if (m) {
            const int slot = running + woff + __popc(bal & ((1u << lane) - 1u));
            if (slot < CAP) {
                const int tok = i >> 1;
                const size_t o = (size_t)tok * (N_EXP * CAP) + e * CAP + slot;
                mask[o] = 1.0f;
                combine[o] = g_topk_val[i];
            }
        }
        running += tot;
        __syncthreads();
    }
    if (tid == 0) g_counts[e] = running;

    // deterministic column sum of probs[:, e]
    float s = 0.0f;
    for (int t = tid; t < N_TOK; t += 256)
        s += probs[(size_t)t * N_EXP + e];
#pragma unroll
    for (int off = 16; off; off >>= 1)
        s += __shfl_xor_sync(0xffffffffu, s, off);
    if (lane == 0) fsum[w] = s;
    __syncthreads();
    if (tid == 0) {
        float t = 0.0f;
#pragma unroll
        for (int j = 0; j < 8; j++) t += fsum[j];
        g_colsum[e] = t;
    }
}

// ---------------------------------------------------------------------------
// Kernel 4: load-balancing loss (scalar).
// ---------------------------------------------------------------------------
__global__ void loss_kernel(float* __restrict__ out_loss) {
    const int e = threadIdx.x;   // 64 threads
    __shared__ float sh[N_EXP];
    sh[e] = ((float)g_counts[e] / (float)(N_TOK * TOPK)) *
            (g_colsum[e] / (float)N_TOK);
    __syncthreads();
    if (e == 0) {
        float s = 0.0f;
#pragma unroll
        for (int j = 0; j < N_EXP; j++) s += sh[j];
        out_loss[0] = 0.01f * (float)N_EXP * s;
    }
}

// ---------------------------------------------------------------------------
extern "C" void kernel_launch(void* const* d_in, const int* in_sizes, int n_in,
                              void* d_out, int out_size) {
    const float* x  = (const float*)d_in[0];
    const float* gw = (const float*)d_in[1];
    if (n_in >= 2 && in_sizes[0] < in_sizes[1]) {  // robustness vs input ordering
        const float* t = x; x = gw; gw = t;
    }
    float* out = (float*)d_out;

    // layout: [dispatch_mask (N,E,C)] [combine_weights (N,E,C)] [probs (N,E)] [loss]
    float* mask    = out;
    float* combine = out + NEC;
    float* probs   = out + 2 * NEC;
    float* loss    = out + 2 * NEC + (size_t)N_TOK * N_EXP;

    // Split-K GEMM (TMA zero-fill fused) -> softmax/top2 -> scan -> loss.
    gemm_partial_kernel<<<2 * (N_TOK / 64), 256>>>(x, gw, out);
    softmax_topk_kernel<<<N_TOK / 8, 256>>>(probs);
    scan_scatter_kernel<<<N_EXP, 256>>>(mask, combine, probs);
    loss_kernel<<<1, N_EXP>>>(loss);
}